// round 2
// baseline (speedup 1.0000x reference)
#include <cuda_runtime.h>

#define NN 3072
#define RR 16

// Per-node pairing code: batch id if node is valid, unique negative sentinel
// otherwise (sentinel never equals another node's code, so invalid nodes
// never pair). Scratch as __device__ global per allocation rules.
__device__ int g_code[NN];

// NOTE: jax default config has x64 disabled, so the reference's
// .astype(jnp.int64) actually produces int32 buffers. Read as int.
__global__ void build_code_kernel(const int* __restrict__ cls,
                                  const int* __restrict__ batch) {
    int i = blockIdx.x * blockDim.x + threadIdx.x;
    if (i < NN) {
        int c = cls[i];
        bool ok = (c != 24) && (c != 25) && (c != 26);
        g_code[i] = ok ? batch[i] : (-1 - i);
    }
}

// One thread per 16B (float4) of output. gid = ((i*N + j) << 2) | q.
// Consecutive threads -> consecutive float4 -> fully coalesced STG.128.
__global__ void __launch_bounds__(256)
pair_write_kernel(const float4* __restrict__ z1,   // [N][4] of float4
                  const float4* __restrict__ z2,   // [N][4] of float4
                  const float* __restrict__ seg,   // [N*N]
                  float4* __restrict__ out)        // [N*N*4]
{
    unsigned gid  = blockIdx.x * 256u + threadIdx.x;   // < N*N*4 = 37,748,736
    unsigned pair = gid >> 2;
    unsigned q    = gid & 3u;
    unsigned i    = pair / NN;
    unsigned j    = pair - i * NN;

    // seg is a read-once 37.7MB stream: streaming load, keep L2 for z1/z2/code.
    float s = __ldcs(seg + pair);

    // seg_matrix + eye: diagonal always nonzero -> i != j required.
    bool hit = (g_code[i] == g_code[j]) && (s == 0.0f) && (i != j);

    float4 v;
    if (hit) {
        float4 a = z1[i * 4u + q];      // hot in L1/L2 (192 KB total)
        float4 b = z2[j * 4u + q];
        v = make_float4(a.x * b.x, a.y * b.y, a.z * b.z, a.w * b.w);
    } else {
        // default = one_hot(0) over R=16: first float of quad 0 is 1, rest 0.
        v = make_float4(q == 0u ? 1.0f : 0.0f, 0.0f, 0.0f, 0.0f);
    }

    __stcs(out + gid, v);               // 604MB write stream
}

extern "C" void kernel_launch(void* const* d_in, const int* in_sizes, int n_in,
                              void* d_out, int out_size) {
    const float4* z1    = (const float4*)d_in[0];
    const float4* z2    = (const float4*)d_in[1];
    const float*  seg   = (const float*)d_in[2];
    const int*    cls   = (const int*)d_in[3];
    const int*    batch = (const int*)d_in[4];
    float4*       out   = (float4*)d_out;

    build_code_kernel<<<(NN + 255) / 256, 256>>>(cls, batch);

    const unsigned total_quads = (unsigned)NN * (unsigned)NN * 4u; // 37,748,736
    pair_write_kernel<<<total_quads / 256u, 256>>>(z1, z2, seg, out);
}

// round 3
// speedup vs baseline: 1.3277x; 1.3277x over previous
#include <cuda_runtime.h>

#define NN 3072u
#define TOTAL_QUADS (NN * NN * 4u)      // 37,748,736 float4 slots
#define UNROLL 4u
#define TPB 256u
// each thread handles UNROLL quads, one in each contiguous quarter-partition
#define SPAN (TOTAL_QUADS / UNROLL)     // 9,437,184

__device__ int g_code[NN];

// jax x64 disabled: int64-labeled inputs are actually int32.
__global__ void build_code_kernel(const int* __restrict__ cls,
                                  const int* __restrict__ batch) {
    int i = blockIdx.x * blockDim.x + threadIdx.x;
    if (i < (int)NN) {
        int c = cls[i];
        bool ok = (c != 24) && (c != 25) && (c != 26);
        g_code[i] = ok ? batch[i] : (-1 - i);
    }
}

// One thread per UNROLL float4s of output, partition-strided so every warp's
// stores stay contiguous (STG.128 -> 4 full 128B lines per warp per store).
// All UNROLL seg loads are issued back-to-back first (MLP_p1 = 4) so the
// DRAM latency of the seg stream is fully overlapped.
__global__ void __launch_bounds__(TPB)
pair_write_kernel(const float4* __restrict__ z1,   // [N][4] float4
                  const float4* __restrict__ z2,   // [N][4] float4
                  const float* __restrict__ seg,   // [N*N]
                  float4* __restrict__ out)        // [N*N*4]
{
    unsigned base = blockIdx.x * TPB + threadIdx.x;   // < SPAN

    unsigned gid[UNROLL], pr[UNROLL], qq[UNROLL], ii[UNROLL], jj[UNROLL];
    float s[UNROLL];

    // Front-batched independent loads: seg stream (read-once -> .cs).
#pragma unroll
    for (unsigned k = 0; k < UNROLL; k++) {
        gid[k] = base + k * SPAN;
        pr[k]  = gid[k] >> 2;
        qq[k]  = gid[k] & 3u;
        s[k]   = __ldcs(seg + pr[k]);
    }

#pragma unroll
    for (unsigned k = 0; k < UNROLL; k++) {
        ii[k] = pr[k] / NN;
        jj[k] = pr[k] - ii[k] * NN;
    }

#pragma unroll
    for (unsigned k = 0; k < UNROLL; k++) {
        // diagonal excluded (seg + eye), invalid nodes carry unique sentinels
        bool hit = (g_code[ii[k]] == g_code[jj[k]])
                 && (s[k] == 0.0f) && (ii[k] != jj[k]);

        float4 v;
        if (hit) {
            float4 a = z1[ii[k] * 4u + qq[k]];   // 192KB working set: L1/L2 hot
            float4 b = z2[jj[k] * 4u + qq[k]];
            v = make_float4(a.x * b.x, a.y * b.y, a.z * b.z, a.w * b.w);
        } else {
            // default row = one_hot(0): 1.0 in float 0 of quad 0, else 0
            v = make_float4(qq[k] == 0u ? 1.0f : 0.0f, 0.0f, 0.0f, 0.0f);
        }
        __stcs(out + gid[k], v);                 // 604MB write stream
    }
}

extern "C" void kernel_launch(void* const* d_in, const int* in_sizes, int n_in,
                              void* d_out, int out_size) {
    const float4* z1    = (const float4*)d_in[0];
    const float4* z2    = (const float4*)d_in[1];
    const float*  seg   = (const float*)d_in[2];
    const int*    cls   = (const int*)d_in[3];
    const int*    batch = (const int*)d_in[4];
    float4*       out   = (float4*)d_out;

    build_code_kernel<<<((int)NN + (int)TPB - 1) / (int)TPB, TPB>>>(cls, batch);

    pair_write_kernel<<<SPAN / TPB, TPB>>>(z1, z2, seg, out);
}